// round 3
// baseline (speedup 1.0000x reference)
#include <cuda_runtime.h>

#define S_     16
#define IND    128
#define OD     64
#define ED     32
#define PN     4          // nodes per block, kernel A
#define ALPHA  0.8f
#define NMAX   50000

#define SN_STRIDE 132     // padded row stride (floats) for neigh tile
#define SE_STRIDE 36      // padded row stride (floats) for edge tile

__device__ float g_wax[IND];     // W  @ a_x
__device__ float g_w2an[IND];    // W2 @ a_n
__device__ float g_agg[(size_t)NMAX * IND];  // attention-aggregated raw neigh features

// packed fp32x2 FMA (sm_103a): d = a*b + d elementwise on 2 packed floats
__device__ __forceinline__ void ffma2(unsigned long long& d,
                                      unsigned long long a,
                                      unsigned long long b) {
    asm("fma.rn.f32x2 %0, %1, %2, %0;" : "+l"(d) : "l"(a), "l"(b));
}
__device__ __forceinline__ unsigned long long splat2(float x) {
    unsigned long long r;
    asm("mov.b64 %0, {%1, %1};" : "=l"(r) : "f"(x));
    return r;
}

// ---------------------------------------------------------------------------
// K0: fold projection vectors — one warp per output element (256 warps)
// ---------------------------------------------------------------------------
__global__ __launch_bounds__(256) void precompute_kernel(
    const float* __restrict__ W,
    const float* __restrict__ W2,
    const float* __restrict__ a)
{
    int gw   = (blockIdx.x * blockDim.x + threadIdx.x) >> 5;
    int lane = threadIdx.x & 31;
    if (gw < 2 * IND) {
        int m = gw >> 7;          // 0 -> W/a_x, 1 -> W2/a_n
        int k = gw & (IND - 1);
        const float* Wm = m ? W2 : W;
        const float* av = m ? (a + OD) : a;
        float s = Wm[k * OD + lane] * av[lane]
                + Wm[k * OD + lane + 32] * av[lane + 32];
#pragma unroll
        for (int o = 16; o; o >>= 1) s += __shfl_down_sync(0xffffffffu, s, o);
        if (lane == 0) (m ? g_w2an : g_wax)[k] = s;
    }
}

// ---------------------------------------------------------------------------
// K1: fused scores + softmax + aggregation (streaming, HBM-bound)
// ---------------------------------------------------------------------------
__global__ __launch_bounds__(256) void attn_kernel(
    const float* __restrict__ input,
    const float* __restrict__ neigh,
    const float* __restrict__ ee,
    const float* __restrict__ a,
    float* __restrict__ out,
    int N)
{
    __shared__ float sN[PN * S_ * SN_STRIDE];   // 8448 f
    __shared__ float sE[PN * S_ * SE_STRIDE];   // 2304 f
    __shared__ float sIn[PN * IND];             // 512 f
    __shared__ float sWax[IND];
    __shared__ float sW2an[IND];
    __shared__ float sAe[ED];
    __shared__ float sScore[PN * S_];
    __shared__ float sC[PN];

    const int tid = threadIdx.x;
    const int n0  = blockIdx.x * PN;

    if (tid < IND) { sWax[tid] = g_wax[tid]; sW2an[tid] = g_w2an[tid]; }
    if (tid < ED)  sAe[tid] = a[2 * OD + tid];

    // stage neigh tile: 64 rows x 128 f = 2048 float4, padded rows of 33 float4
    {
        const float4* gN = (const float4*)(neigh + (size_t)n0 * S_ * IND);
        float4* s4 = (float4*)sN;
#pragma unroll
        for (int it = 0; it < 8; ++it) {
            int idx = tid + 256 * it;
            int r = idx >> 5, c = idx & 31;
            s4[r * 33 + c] = gN[idx];
        }
    }
    // stage edge tile: 64 rows x 32 f = 512 float4, padded rows of 9 float4
    {
        const float4* gE = (const float4*)(ee + (size_t)n0 * S_ * ED);
        float4* e4 = (float4*)sE;
#pragma unroll
        for (int it = 0; it < 2; ++it) {
            int idx = tid + 256 * it;
            int r = idx >> 3, c = idx & 7;
            e4[r * 9 + c] = gE[idx];
        }
    }
    // stage input rows: 512 f = 128 float4
    if (tid < 128)
        ((float4*)sIn)[tid] = ((const float4*)(input + (size_t)n0 * IND))[tid];

    __syncthreads();

    // c[p] = input_row . (W a_x)   — one warp per node
    if (tid < PN * 32) {
        int p = tid >> 5, l = tid & 31;
        float c = 0.f;
#pragma unroll
        for (int i = 0; i < IND / 32; ++i)
            c += sIn[p * IND + l + 32 * i] * sWax[l + 32 * i];
#pragma unroll
        for (int o = 16; o; o >>= 1) c += __shfl_down_sync(0xffffffffu, c, o);
        if (l == 0) sC[p] = c;
    }

    // raw scores: 64 (node,s) rows, 4 lanes each (padded strides -> conflict-free)
    {
        int g = tid >> 2, j = tid & 3;   // g = p*S + s
        float sc = 0.f;
        const float* nr = &sN[g * SN_STRIDE];
#pragma unroll
        for (int i = 0; i < IND / 4; ++i) sc += nr[j + 4 * i] * sW2an[j + 4 * i];
        const float* er = &sE[g * SE_STRIDE];
#pragma unroll
        for (int i = 0; i < ED / 4; ++i)  sc += er[j + 4 * i] * sAe[j + 4 * i];
        sc += __shfl_down_sync(0xffffffffu, sc, 2, 4);
        sc += __shfl_down_sync(0xffffffffu, sc, 1, 4);
        if (j == 0) sScore[g] = sc;
    }
    __syncthreads();

    // leaky-relu + softmax over S (one thread per node; S=16 serial)
    if (tid < PN) {
        float c = sC[tid];
        float e[S_];
        float mx = -1e30f;
#pragma unroll
        for (int s = 0; s < S_; ++s) {
            float v = sScore[tid * S_ + s] + c;
            v = v > 0.f ? v : ALPHA * v;
            e[s] = v;
            mx = fmaxf(mx, v);
        }
        float sum = 0.f;
#pragma unroll
        for (int s = 0; s < S_; ++s) { e[s] = __expf(e[s] - mx); sum += e[s]; }
        float inv = 1.f / sum;
#pragma unroll
        for (int s = 0; s < S_; ++s) sScore[tid * S_ + s] = e[s] * inv;
    }
    __syncthreads();

    // aggregate raw neigh features -> g_agg  (512 outputs)
#pragma unroll
    for (int it = 0; it < 2; ++it) {
        int t = tid + 256 * it;
        int p = t >> 7, k = t & 127;
        float acc = 0.f;
#pragma unroll
        for (int s = 0; s < S_; ++s)
            acc += sScore[p * S_ + s] * sN[(p * S_ + s) * SN_STRIDE + k];
        g_agg[(size_t)(n0 + p) * IND + k] = acc;
    }
    // aggregate edges -> out cols [128,160)
    if (tid < PN * ED) {
        int p = tid >> 5, e_ = tid & 31;
        float acc = 0.f;
#pragma unroll
        for (int s = 0; s < S_; ++s)
            acc += sScore[p * S_ + s] * sE[(p * S_ + s) * SE_STRIDE + e_];
        out[(size_t)(n0 + p) * 160 + 128 + e_] = acc;
    }
}

// ---------------------------------------------------------------------------
// K2: out[:,0:64] = input @ W ; out[:,64:128] = agg @ W2
//     64 nodes/block, 256 threads, 8d x 2n per thread, packed f32x2 FMA
// ---------------------------------------------------------------------------
__global__ __launch_bounds__(256) void proj_kernel(
    const float* __restrict__ input,
    const float* __restrict__ W,
    const float* __restrict__ W2,
    float* __restrict__ out,
    int N)
{
    extern __shared__ float smem[];
    float* sW = smem;            // 128*64 = 8192 f (32 KB), [k][d]
    float* sX = smem + 8192;     // 64*128 = 8192 f (32 KB), [n][k]

    const int tid = threadIdx.x;
    const int dx  = tid & 7;     // d-octet: d = dx*8 .. dx*8+7
    const int ny  = tid >> 3;    // node lane 0..31; nodes ny, ny+32
    const int n0  = blockIdx.x * 64;

#pragma unroll
    for (int m = 0; m < 2; ++m) {
        const float* Wm = m ? W2 : W;
        const float* Xm = m ? g_agg : input;

        // stage W tile (2048 float4) and X tile (2048 float4, guarded)
        {
            const float4* gW = (const float4*)Wm;
            float4* s4 = (float4*)sW;
#pragma unroll
            for (int it = 0; it < 8; ++it) s4[tid + 256 * it] = gW[tid + 256 * it];

            const float4* gX = (const float4*)Xm;
            float4* x4 = (float4*)sX;
            float4 z; z.x = z.y = z.z = z.w = 0.f;
#pragma unroll
            for (int it = 0; it < 8; ++it) {
                int idx = tid + 256 * it;
                int r = idx >> 5, c = idx & 31;
                int nn = n0 + r;
                x4[idx] = (nn < N) ? gX[(size_t)nn * 32 + c] : z;
            }
        }
        __syncthreads();

        // acc[i][q] packs d = dx*8 + 2q, dx*8 + 2q + 1 for node ny + 32*i
        unsigned long long acc[2][4];
#pragma unroll
        for (int i = 0; i < 2; ++i)
#pragma unroll
            for (int q = 0; q < 4; ++q) acc[i][q] = 0ull;

        const ulonglong2* sWp = (const ulonglong2*)sW;   // pairs of packed floats
#pragma unroll 8
        for (int k = 0; k < IND; ++k) {
            ulonglong2 wa = sWp[k * 16 + dx * 2];        // d: 8dx+0..3
            ulonglong2 wb = sWp[k * 16 + dx * 2 + 1];    // d: 8dx+4..7
#pragma unroll
            for (int i = 0; i < 2; ++i) {
                unsigned long long x2 = splat2(sX[(ny + 32 * i) * IND + k]);
                ffma2(acc[i][0], wa.x, x2);
                ffma2(acc[i][1], wa.y, x2);
                ffma2(acc[i][2], wb.x, x2);
                ffma2(acc[i][3], wb.y, x2);
            }
        }

#pragma unroll
        for (int i = 0; i < 2; ++i) {
            int nn = n0 + ny + 32 * i;
            if (nn < N) {
                float* dst = &out[(size_t)nn * 160 + m * 64 + dx * 8];
                ((ulonglong2*)dst)[0] = make_ulonglong2(acc[i][0], acc[i][1]);
                ((ulonglong2*)dst)[1] = make_ulonglong2(acc[i][2], acc[i][3]);
            }
        }
        __syncthreads();
    }
}

// ---------------------------------------------------------------------------
extern "C" void kernel_launch(void* const* d_in, const int* in_sizes, int n_in,
                              void* d_out, int out_size) {
    const float* input = (const float*)d_in[0];
    const float* neigh = (const float*)d_in[1];
    const float* ee    = (const float*)d_in[2];
    const float* W     = (const float*)d_in[3];
    const float* W2    = (const float*)d_in[4];
    const float* a     = (const float*)d_in[5];
    float* out = (float*)d_out;

    int N = in_sizes[0] / IND;      // 50000

    static bool attr_set = false;
    if (!attr_set) {
        cudaFuncSetAttribute(proj_kernel,
                             cudaFuncAttributeMaxDynamicSharedMemorySize,
                             2 * 8192 * (int)sizeof(float));
        attr_set = true;
    }

    precompute_kernel<<<32, 256>>>(W, W2, a);
    attn_kernel<<<N / PN, 256>>>(input, neigh, ee, a, out, N);
    proj_kernel<<<(N + 63) / 64, 256, 2 * 8192 * sizeof(float)>>>(input, W, W2, out, N);
}

// round 4
// speedup vs baseline: 1.4516x; 1.4516x over previous
#include <cuda_runtime.h>

#define S_     16
#define IND    128
#define OD     64
#define ED     32
#define PN     4          // nodes per block, kernel A
#define ALPHA  0.8f
#define NMAX   50000

#define SN_STRIDE 132     // padded row stride (floats) for neigh tile
#define SE_STRIDE 36      // padded row stride (floats) for edge tile

__device__ float g_wax[IND];     // W  @ a_x
__device__ float g_w2an[IND];    // W2 @ a_n
__device__ float g_agg[(size_t)NMAX * IND];  // attention-aggregated raw neigh features

// ---------------------------------------------------------------------------
// K0: fold projection vectors — one warp per output element (256 warps)
// ---------------------------------------------------------------------------
__global__ __launch_bounds__(256) void precompute_kernel(
    const float* __restrict__ W,
    const float* __restrict__ W2,
    const float* __restrict__ a)
{
    int gw   = (blockIdx.x * blockDim.x + threadIdx.x) >> 5;
    int lane = threadIdx.x & 31;
    if (gw < 2 * IND) {
        int m = gw >> 7;          // 0 -> W/a_x, 1 -> W2/a_n
        int k = gw & (IND - 1);
        const float* Wm = m ? W2 : W;
        const float* av = m ? (a + OD) : a;
        float s = Wm[k * OD + lane] * av[lane]
                + Wm[k * OD + lane + 32] * av[lane + 32];
#pragma unroll
        for (int o = 16; o; o >>= 1) s += __shfl_down_sync(0xffffffffu, s, o);
        if (lane == 0) (m ? g_w2an : g_wax)[k] = s;
    }
}

// ---------------------------------------------------------------------------
// K1: fused scores + softmax + aggregation (streaming, HBM-bound)
// ---------------------------------------------------------------------------
__global__ __launch_bounds__(256) void attn_kernel(
    const float* __restrict__ input,
    const float* __restrict__ neigh,
    const float* __restrict__ ee,
    const float* __restrict__ a,
    float* __restrict__ out,
    int N)
{
    __shared__ float sN[PN * S_ * SN_STRIDE];   // 8448 f
    __shared__ float sE[PN * S_ * SE_STRIDE];   // 2304 f
    __shared__ float sIn[PN * IND];             // 512 f
    __shared__ float sWax[IND];
    __shared__ float sW2an[IND];
    __shared__ float sAe[ED];
    __shared__ float sScore[PN * S_];
    __shared__ float sC[PN];

    const int tid = threadIdx.x;
    const int n0  = blockIdx.x * PN;

    if (tid < IND) { sWax[tid] = g_wax[tid]; sW2an[tid] = g_w2an[tid]; }
    if (tid < ED)  sAe[tid] = a[2 * OD + tid];

    // stage neigh tile: 64 rows x 128 f = 2048 float4, padded rows of 33 float4
    {
        const float4* gN = (const float4*)(neigh + (size_t)n0 * S_ * IND);
        float4* s4 = (float4*)sN;
#pragma unroll
        for (int it = 0; it < 8; ++it) {
            int idx = tid + 256 * it;
            int r = idx >> 5, c = idx & 31;
            s4[r * 33 + c] = gN[idx];
        }
    }
    // stage edge tile: 64 rows x 32 f = 512 float4, padded rows of 9 float4
    {
        const float4* gE = (const float4*)(ee + (size_t)n0 * S_ * ED);
        float4* e4 = (float4*)sE;
#pragma unroll
        for (int it = 0; it < 2; ++it) {
            int idx = tid + 256 * it;
            int r = idx >> 3, c = idx & 7;
            e4[r * 9 + c] = gE[idx];
        }
    }
    // stage input rows: 512 f = 128 float4
    if (tid < 128)
        ((float4*)sIn)[tid] = ((const float4*)(input + (size_t)n0 * IND))[tid];

    __syncthreads();

    // c[p] = input_row . (W a_x)   — one warp per node
    if (tid < PN * 32) {
        int p = tid >> 5, l = tid & 31;
        float c = 0.f;
#pragma unroll
        for (int i = 0; i < IND / 32; ++i)
            c += sIn[p * IND + l + 32 * i] * sWax[l + 32 * i];
#pragma unroll
        for (int o = 16; o; o >>= 1) c += __shfl_down_sync(0xffffffffu, c, o);
        if (l == 0) sC[p] = c;
    }

    // raw scores: 64 (node,s) rows, 4 lanes each (padded strides -> conflict-free)
    {
        int g = tid >> 2, j = tid & 3;   // g = p*S + s
        float sc = 0.f;
        const float* nr = &sN[g * SN_STRIDE];
#pragma unroll
        for (int i = 0; i < IND / 4; ++i) sc += nr[j + 4 * i] * sW2an[j + 4 * i];
        const float* er = &sE[g * SE_STRIDE];
#pragma unroll
        for (int i = 0; i < ED / 4; ++i)  sc += er[j + 4 * i] * sAe[j + 4 * i];
        sc += __shfl_down_sync(0xffffffffu, sc, 2, 4);
        sc += __shfl_down_sync(0xffffffffu, sc, 1, 4);
        if (j == 0) sScore[g] = sc;
    }
    __syncthreads();

    // leaky-relu + softmax over S (one thread per node; S=16 serial)
    if (tid < PN) {
        float c = sC[tid];
        float e[S_];
        float mx = -1e30f;
#pragma unroll
        for (int s = 0; s < S_; ++s) {
            float v = sScore[tid * S_ + s] + c;
            v = v > 0.f ? v : ALPHA * v;
            e[s] = v;
            mx = fmaxf(mx, v);
        }
        float sum = 0.f;
#pragma unroll
        for (int s = 0; s < S_; ++s) { e[s] = __expf(e[s] - mx); sum += e[s]; }
        float inv = 1.f / sum;
#pragma unroll
        for (int s = 0; s < S_; ++s) sScore[tid * S_ + s] = e[s] * inv;
    }
    __syncthreads();

    // aggregate raw neigh features -> g_agg  (512 outputs)
#pragma unroll
    for (int it = 0; it < 2; ++it) {
        int t = tid + 256 * it;
        int p = t >> 7, k = t & 127;
        float acc = 0.f;
#pragma unroll
        for (int s = 0; s < S_; ++s)
            acc += sScore[p * S_ + s] * sN[(p * S_ + s) * SN_STRIDE + k];
        g_agg[(size_t)(n0 + p) * IND + k] = acc;
    }
    // aggregate edges -> out cols [128,160)
    if (tid < PN * ED) {
        int p = tid >> 5, e_ = tid & 31;
        float acc = 0.f;
#pragma unroll
        for (int s = 0; s < S_; ++s)
            acc += sScore[p * S_ + s] * sE[(p * S_ + s) * SE_STRIDE + e_];
        out[(size_t)(n0 + p) * 160 + 128 + e_] = acc;
    }
}

// ---------------------------------------------------------------------------
// K2: out[:,0:64] = input @ W ; out[:,64:128] = agg @ W2
//     64 nodes/block, 256 threads, shared W tile + X tile, 4d x 4n reg blocking
//     (reverted to the verified R1 structure: scalar FFMA at the fma-pipe roofline)
// ---------------------------------------------------------------------------
__global__ __launch_bounds__(256) void proj_kernel(
    const float* __restrict__ input,
    const float* __restrict__ W,
    const float* __restrict__ W2,
    float* __restrict__ out,
    int N)
{
    extern __shared__ float smem[];
    float* sW = smem;            // 128*64 = 8192 f (32 KB), [k][d]
    float* sX = smem + 8192;     // 64*128 = 8192 f (32 KB), [n][k]

    const int tid = threadIdx.x;
    const int dx  = tid & 15;    // d-quad: d = dx*4 .. dx*4+3
    const int ny  = tid >> 4;    // node lane 0..15; nodes ny + 16*i
    const int n0  = blockIdx.x * 64;

#pragma unroll
    for (int m = 0; m < 2; ++m) {
        const float* Wm = m ? W2 : W;
        const float* Xm = m ? g_agg : input;

        // stage W tile (2048 float4) and X tile (2048 float4, guarded)
        {
            const float4* gW = (const float4*)Wm;
            float4* s4 = (float4*)sW;
#pragma unroll
            for (int it = 0; it < 8; ++it) s4[tid + 256 * it] = gW[tid + 256 * it];

            const float4* gX = (const float4*)Xm;
            float4* x4 = (float4*)sX;
            float4 z; z.x = z.y = z.z = z.w = 0.f;
#pragma unroll
            for (int it = 0; it < 8; ++it) {
                int idx = tid + 256 * it;
                int r = idx >> 5, c = idx & 31;
                int nn = n0 + r;
                x4[idx] = (nn < N) ? gX[(size_t)nn * 32 + c] : z;
            }
        }
        __syncthreads();

        float4 acc[4];
#pragma unroll
        for (int i = 0; i < 4; ++i) { acc[i].x = acc[i].y = acc[i].z = acc[i].w = 0.f; }

        const float4* sW4 = (const float4*)sW;
#pragma unroll 4
        for (int k = 0; k < IND; ++k) {
            float4 w = sW4[k * 16 + dx];
#pragma unroll
            for (int i = 0; i < 4; ++i) {
                float xv = sX[(ny + 16 * i) * IND + k];
                acc[i].x += xv * w.x;
                acc[i].y += xv * w.y;
                acc[i].z += xv * w.z;
                acc[i].w += xv * w.w;
            }
        }

#pragma unroll
        for (int i = 0; i < 4; ++i) {
            int nn = n0 + ny + 16 * i;
            if (nn < N)
                *(float4*)&out[(size_t)nn * 160 + m * 64 + dx * 4] = acc[i];
        }
        __syncthreads();
    }
}

// ---------------------------------------------------------------------------
extern "C" void kernel_launch(void* const* d_in, const int* in_sizes, int n_in,
                              void* d_out, int out_size) {
    const float* input = (const float*)d_in[0];
    const float* neigh = (const float*)d_in[1];
    const float* ee    = (const float*)d_in[2];
    const float* W     = (const float*)d_in[3];
    const float* W2    = (const float*)d_in[4];
    const float* a     = (const float*)d_in[5];
    float* out = (float*)d_out;

    int N = in_sizes[0] / IND;      // 50000

    static bool attr_set = false;
    if (!attr_set) {
        cudaFuncSetAttribute(proj_kernel,
                             cudaFuncAttributeMaxDynamicSharedMemorySize,
                             2 * 8192 * (int)sizeof(float));
        attr_set = true;
    }

    precompute_kernel<<<32, 256>>>(W, W2, a);
    attn_kernel<<<N / PN, 256>>>(input, neigh, ee, a, out, N);
    proj_kernel<<<(N + 63) / 64, 256, 2 * 8192 * sizeof(float)>>>(input, W, W2, out, N);
}